// round 10
// baseline (speedup 1.0000x reference)
#include <cuda_runtime.h>

// Bidirectional LSTM, B=16, S=4096, H=F=256.
// 128 persistent CTAs: dir = blockIdx.x>>6, slice = blockIdx.x&63.
// Each CTA owns 4 h-columns -> 16 z-columns. Wh/Wi column slices live in
// REGISTERS (packed f32x2). Dots read activations DIRECTLY (h via ld.cg from
// L2, x via L1-cacheable loads) — no SMEM staging, no gather phase.
// Sync: monotonic atomicAdd counter -> gen (R5/R8-proven), per-warp volatile
// poll with nanosleep backoff. Epilogue (warps 0-1) overlaps x-dot (warps 2-7).

#define BB 16
#define SS 4096
#define HH 256
#define FF 256
#define G4 1024
#define NSL 64
#define NT 256

__device__ float    g_hbuf[2][2][BB * FF];   // [dir][parity t&1][b*F + col]
__device__ unsigned g_cnt[2][32];            // monotonic arrival counters
__device__ unsigned g_gen[2][32];            // completed-step generation

__device__ __forceinline__ void fma2(unsigned long long &acc,
                                     unsigned long long a, unsigned long long w) {
    asm("fma.rn.f32x2 %0, %1, %2, %0;" : "+l"(acc) : "l"(a), "l"(w));
}
__device__ __forceinline__ unsigned long long pk2(float lo, float hi) {
    unsigned long long r;
    asm("mov.b64 %0, {%1,%2};" : "=l"(r) : "f"(lo), "f"(hi));
    return r;
}
__device__ __forceinline__ float red2(unsigned long long p) {
    float lo, hi;
    asm("mov.b64 {%0,%1}, %2;" : "=f"(lo), "=f"(hi) : "l"(p));
    return lo + hi;
}
__device__ __forceinline__ float sigm(float x) {
    return 1.0f / (1.0f + __expf(-x));
}
__device__ __forceinline__ float tanh_fast(float x) {
    return 1.0f - 2.0f / (__expf(2.0f * x) + 1.0f);
}
// 16B L2 load (bypass L1 — h is written by other SMs each step).
__device__ __forceinline__ ulonglong2 ldcg2(const void* p) {
    ulonglong2 v;
    asm("ld.global.cg.v2.u64 {%0,%1}, [%2];" : "=l"(v.x), "=l"(v.y) : "l"(p));
    return v;
}

__global__ void lstm_init_kernel() {
    if (threadIdx.x < 2) {
        g_cnt[threadIdx.x][0] = 0u;
        g_gen[threadIdx.x][0] = 0u;
    }
}

__global__ void __launch_bounds__(NT, 1) lstm_scan_kernel(
    const float* __restrict__ x,
    const float* __restrict__ Wi_fw, const float* __restrict__ Wh_fw,
    const float* __restrict__ b_fw,
    const float* __restrict__ Wi_rv, const float* __restrict__ Wh_rv,
    const float* __restrict__ b_rv,
    float* __restrict__ out, int write_finals)
{
    __shared__ float zb[BB * 16];
    __shared__ float cst[64];

    const int bx   = blockIdx.x;
    const int dd   = bx >> 6;
    const int sl   = bx & 63;
    const int tid  = threadIdx.x;
    const int lane = tid & 31;
    const int p    = tid >> 6;          // warp pair: batches 4p..4p+3
    const int half = (tid >> 5) & 1;    // which 8 of the 16 cols
    const int col8 = lane & 7;
    const int kc   = lane >> 3;         // k-chunk 0..3 (64 k each)
    const int cc   = (half << 3) + col8;            // local z-col 0..15
    const int colg = ((cc >> 2) << 8) + (sl << 2) + (cc & 3);

    const float* Wi = dd ? Wi_rv : Wi_fw;
    const float* Wh = dd ? Wh_rv : Wh_fw;
    const float bcc = (dd ? b_rv : b_fw)[colg];

    // This thread's weight slice in registers, pre-packed for f32x2.
    // wh2[j] covers k = kc*64 + 2j, 2j+1 (so load j<<4 bytes -> wh2[2j],wh2[2j+1]).
    unsigned long long wh2[32], wi2[32];
#pragma unroll
    for (int j = 0; j < 32; ++j) {
        int k = (kc << 6) + (j << 1);
        wh2[j] = pk2(Wh[(size_t)k * G4 + colg], Wh[(size_t)(k + 1) * G4 + colg]);
        wi2[j] = pk2(Wi[(size_t)k * G4 + colg], Wi[(size_t)(k + 1) * G4 + colg]);
    }

    if (tid < 64) cst[tid] = 0.0f;                          // c0 = 0

    // Initial x-projection (step 0) straight from global (L1-cacheable).
    float accx[4];
    {
        int s0 = dd ? (SS - 1) : 0;
#pragma unroll
        for (int i = 0; i < 4; ++i) {
            int b = (p << 2) + i;
            const ulonglong2* xp = (const ulonglong2*)
                (x + ((size_t)b * SS + s0) * HH + (kc << 6));
            unsigned long long a0 = 0ull, a1 = 0ull;
#pragma unroll
            for (int j = 0; j < 16; ++j) {
                ulonglong2 v = xp[j];
                fma2(a0, v.x, wi2[2 * j]);
                fma2(a1, v.y, wi2[2 * j + 1]);
            }
            float s = red2(a0) + red2(a1);
            s += __shfl_xor_sync(0xffffffffu, s, 8);
            s += __shfl_xor_sync(0xffffffffu, s, 16);
            accx[i] = bcc + s;
        }
    }
    __syncthreads();

    for (int t = 0; t < SS; ++t) {
        // Wait for h(t-1): per-warp poll of generation (all lanes, uniform).
        if (t > 0) {
            volatile unsigned* gp = &g_gen[dd][0];
            if (*gp < (unsigned)t) {
                while (*gp < (unsigned)t) __nanosleep(32);
            }
            __threadfence();   // acquire: gen read before h reads
        }

        // h-dot directly from L2: z = accx + h(t-1) @ Wh[:, colg]
        const char* hbase = (const char*)&g_hbuf[dd][(t + 1) & 1][0];  // parity (t-1)&1
#pragma unroll
        for (int i = 0; i < 4; ++i) {
            float z;
            if (t > 0) {
                int b = (p << 2) + i;
                const char* hp = hbase + (((b << 8) + (kc << 6)) << 2);
                unsigned long long a0 = 0ull, a1 = 0ull;
#pragma unroll
                for (int j = 0; j < 16; ++j) {
                    ulonglong2 v = ldcg2(hp + (j << 4));
                    fma2(a0, v.x, wh2[2 * j]);
                    fma2(a1, v.y, wh2[2 * j + 1]);
                }
                float s = red2(a0) + red2(a1);
                s += __shfl_xor_sync(0xffffffffu, s, 8);
                s += __shfl_xor_sync(0xffffffffu, s, 16);
                z = accx[i] + s;
            } else {
                z = accx[i];               // h(-1) = 0
            }
            if (lane < 8) zb[(((p << 2) + i) << 4) + cc] = z;
        }
        __syncthreads();

        // Warps 0-1: gate epilogue + publish + arrive. Warps 2-7 fall through
        // to the x-dot immediately (overlap).
        int s_cur = dd ? (SS - 1 - t) : t;
        if (tid < 64) {
            int b2 = tid >> 2, hc = tid & 3;
            float zi = zb[(b2 << 4) + 0  + hc];
            float zf = zb[(b2 << 4) + 4  + hc];
            float zg = zb[(b2 << 4) + 8  + hc];
            float zo = zb[(b2 << 4) + 12 + hc];
            float cp = cst[tid];
            float cn = sigm(zf) * cp + sigm(zi) * tanh_fast(zg);
            float hn = sigm(zo) * tanh_fast(cn);
            cst[tid] = cn;
            int col = (sl << 2) + hc;
            g_hbuf[dd][t & 1][(b2 << 8) + col] = hn;
            out[((size_t)b2 * SS + s_cur) * (2 * FF) + dd * FF + col] = hn;
            if (t == SS - 1 && write_finals) {
                size_t base = (size_t)BB * SS * 2 * FF + (size_t)dd * 2 * BB * FF;
                out[base + b2 * FF + col]           = cn;  // c_final
                out[base + BB * FF + b2 * FF + col] = hn;  // h_final
            }
            __threadfence();                    // publish h before arrival
            asm volatile("bar.sync 1, 64;" ::: "memory");   // warps 0-1 only
            if (tid == 0) {
                unsigned old = atomicAdd(&g_cnt[dd][0], 1u);
                if ((old & 63u) == 63u) {       // last of 64: bump generation
                    __threadfence();
                    atomicAdd(&g_gen[dd][0], 1u);
                }
            }
        }
        if (t == SS - 1) break;

        // x-projection for step t+1 (global loads, L1-cacheable; pair partner
        // warp re-reads the same rows -> L1 hit).
        {
            int sn = dd ? (SS - 2 - t) : (t + 1);
#pragma unroll
            for (int i = 0; i < 4; ++i) {
                int b = (p << 2) + i;
                const ulonglong2* xp = (const ulonglong2*)
                    (x + ((size_t)b * SS + sn) * HH + (kc << 6));
                unsigned long long a0 = 0ull, a1 = 0ull;
#pragma unroll
                for (int j = 0; j < 16; ++j) {
                    ulonglong2 v = xp[j];
                    fma2(a0, v.x, wi2[2 * j]);
                    fma2(a1, v.y, wi2[2 * j + 1]);
                }
                float s = red2(a0) + red2(a1);
                s += __shfl_xor_sync(0xffffffffu, s, 8);
                s += __shfl_xor_sync(0xffffffffu, s, 16);
                accx[i] = bcc + s;
            }
        }
        __syncthreads();   // zb/cst protection before next step's writes
    }
}

extern "C" void kernel_launch(void* const* d_in, const int* in_sizes, int n_in,
                              void* d_out, int out_size) {
    const float* x     = (const float*)d_in[0];
    const float* Wi_fw = (const float*)d_in[1];
    const float* Wh_fw = (const float*)d_in[2];
    const float* b_fw  = (const float*)d_in[3];
    const float* Wi_rv = (const float*)d_in[4];
    const float* Wh_rv = (const float*)d_in[5];
    const float* b_rv  = (const float*)d_in[6];
    float* out = (float*)d_out;

    int write_finals = (out_size >= (int)((size_t)BB * SS * 2 * FF + 4 * BB * FF)) ? 1 : 0;

    lstm_init_kernel<<<1, 32>>>();
    lstm_scan_kernel<<<2 * NSL, NT>>>(x, Wi_fw, Wh_fw, b_fw,
                                      Wi_rv, Wh_rv, b_rv, out, write_finals);
}

// round 13
// speedup vs baseline: 1.5733x; 1.5733x over previous
#include <cuda_runtime.h>

// Bidirectional LSTM, B=16, S=4096, H=F=256.
// 128 persistent CTAs: dir = blockIdx.x>>6, slice = blockIdx.x&63.
// Each CTA owns 4 h-columns -> 16 z-columns. Wh/Wi column slices in REGISTERS
// (packed f32x2). WARP-AUTONOMOUS steps: each warp gathers its pair's 4 h rows
// into a warp-PRIVATE interleaved SMEM buffer (coalesced ld.cg), syncwarp,
// broadcast-LDS dot. Pair-local epilogue; arrival = per-pair REDG on a global
// counter after per-lane fence + __syncwarp. 256 arrivals/step/direction.
// R12 fix: x staging source address had a duplicated i*256 batch term that
// aliased to timestep sn+i (deterministic rel_err 1.06 in R10/R11).

#define BB 16
#define SS 4096
#define HH 256
#define FF 256
#define G4 1024
#define NSL 64
#define NT 256

__device__ float    g_hbuf[2][2][BB * FF];   // [dir][parity t&1][b*F + col]
__device__ unsigned g_cnt[2][32];            // monotonic arrivals (256 per step)

__device__ __forceinline__ void fma2(unsigned long long &acc,
                                     unsigned long long a, unsigned long long w) {
    asm("fma.rn.f32x2 %0, %1, %2, %0;" : "+l"(acc) : "l"(a), "l"(w));
}
__device__ __forceinline__ unsigned long long pk2(float lo, float hi) {
    unsigned long long r;
    asm("mov.b64 %0, {%1,%2};" : "=l"(r) : "f"(lo), "f"(hi));
    return r;
}
__device__ __forceinline__ float red2(unsigned long long p) {
    float lo, hi;
    asm("mov.b64 {%0,%1}, %2;" : "=f"(lo), "=f"(hi) : "l"(p));
    return lo + hi;
}
__device__ __forceinline__ float sigm(float x) {
    return 1.0f / (1.0f + __expf(-x));
}
__device__ __forceinline__ float tanh_fast(float x) {
    return 1.0f - 2.0f / (__expf(2.0f * x) + 1.0f);
}

__global__ void lstm_init_kernel() {
    if (threadIdx.x < 2) g_cnt[threadIdx.x][0] = 0u;
}

__global__ void __launch_bounds__(NT, 1) lstm_scan_kernel(
    const float* __restrict__ x,
    const float* __restrict__ Wi_fw, const float* __restrict__ Wh_fw,
    const float* __restrict__ b_fw,
    const float* __restrict__ Wi_rv, const float* __restrict__ Wh_rv,
    const float* __restrict__ b_rv,
    float* __restrict__ out, int write_finals)
{
    // Warp-private activation buffers, interleaved layout within each row:
    // float offset = i*256 + j*16 + kc*4  holds source k = kc*64 + j*4 .. +3
    __shared__ __align__(16) float hbw[8][4 * HH];   // 32 KB
    __shared__ float zbuf[4][4][16];                 // [pair][batch][z-col]

    const int bx   = blockIdx.x;
    const int dd   = bx >> 6;
    const int sl   = bx & 63;
    const int tid  = threadIdx.x;
    const int w    = tid >> 5;
    const int lane = tid & 31;
    const int p    = w >> 1;            // pair: batches 4p..4p+3
    const int half = w & 1;             // which 8 of the 16 z-cols
    const int col8 = lane & 7;
    const int kc   = lane >> 3;         // k-chunk 0..3 (64 k each)
    const int cc   = (half << 3) + col8;            // local z-col 0..15
    const int colg = ((cc >> 2) << 8) + (sl << 2) + (cc & 3);

    const float* Wi = dd ? Wi_rv : Wi_fw;
    const float* Wh = dd ? Wh_rv : Wh_fw;
    const float bcc = (dd ? b_rv : b_fw)[colg];

    // Weight slices in registers, pre-packed for f32x2.
    unsigned long long wh2[32], wi2[32];
#pragma unroll
    for (int j = 0; j < 32; ++j) {
        int k = (kc << 6) + (j << 1);
        wh2[j] = pk2(Wh[(size_t)k * G4 + colg], Wh[(size_t)(k + 1) * G4 + colg]);
        wi2[j] = pk2(Wi[(size_t)k * G4 + colg], Wi[(size_t)(k + 1) * G4 + colg]);
    }

    float creg = 0.0f;                                   // c-state in register

    __syncthreads();                                     // only pre-loop sync

    float* hw = hbw[w];

    // Gather x(step 0) into private buffer (interleaved), then x-project.
    // Chunk m = r*32+lane; i = m>>6 (local row); off = m&63;
    // ksrc = (off&3)*64 + (off>>2)*4  — batch offset ONLY via ((p<<2)+i)*SS.
    {
        int s0 = dd ? (SS - 1) : 0;
#pragma unroll
        for (int r = 0; r < 8; ++r) {
            int m = (r << 5) + lane;
            int i = m >> 6, off = m & 63;
            int ksrc = ((off & 3) << 6) + ((off >> 2) << 2);
            *(float4*)(hw + (m << 2)) =
                *(const float4*)(x + ((size_t)((p << 2) + i) * SS + s0) * HH + ksrc);
        }
    }
    __syncwarp();
    float accx[4];
#pragma unroll
    for (int i = 0; i < 4; ++i) {
        const float* vp = hw + (i << 8) + (kc << 2);
        unsigned long long a0 = 0ull, a1 = 0ull;
#pragma unroll
        for (int j = 0; j < 16; ++j) {
            ulonglong2 v = *(const ulonglong2*)(vp + (j << 4));
            fma2(a0, v.x, wi2[2 * j]);
            fma2(a1, v.y, wi2[2 * j + 1]);
        }
        float s = red2(a0) + red2(a1);
        s += __shfl_xor_sync(0xffffffffu, s, 8);
        s += __shfl_xor_sync(0xffffffffu, s, 16);
        accx[i] = bcc + s;
    }

    for (int t = 0; t < SS; ++t) {
        if (t > 0) {
            // Wait for all 256 pair-arrivals of step t-1 (monotonic counter).
            volatile unsigned* gp = &g_cnt[dd][0];
            unsigned tgt = (unsigned)(t << 8);
            if (*gp < tgt) {
                while (*gp < tgt) __nanosleep(64);
            }
            __threadfence();                 // acquire before h reads
            __syncwarp();                    // buffer WAR vs x-dot reads

            // Gather h(t-1) rows 4p..4p+3 into private buffer (interleaved).
            // g_hbuf rows are 256 floats, so batch offset IS (b<<8) here.
            const float* hsrc = &g_hbuf[dd][(t + 1) & 1][0];
#pragma unroll
            for (int r = 0; r < 8; ++r) {
                int m = (r << 5) + lane;
                int i = m >> 6, off = m & 63;
                int src = (((p << 2) + i) << 8) + ((off & 3) << 6) + ((off >> 2) << 2);
                float4 hv = __ldcg((const float4*)(hsrc + src));
                *(float4*)(hw + (m << 2)) = hv;
            }
            __syncwarp();

            // h-dot: z = accx + h(t-1) @ Wh[:, colg]
#pragma unroll
            for (int i = 0; i < 4; ++i) {
                const float* vp = hw + (i << 8) + (kc << 2);
                unsigned long long a0 = 0ull, a1 = 0ull;
#pragma unroll
                for (int j = 0; j < 16; ++j) {
                    ulonglong2 v = *(const ulonglong2*)(vp + (j << 4));
                    fma2(a0, v.x, wh2[2 * j]);
                    fma2(a1, v.y, wh2[2 * j + 1]);
                }
                float s = red2(a0) + red2(a1);
                s += __shfl_xor_sync(0xffffffffu, s, 8);
                s += __shfl_xor_sync(0xffffffffu, s, 16);
                if (lane < 8) zbuf[p][i][cc] = accx[i] + s;
            }
        } else {
#pragma unroll
            for (int i = 0; i < 4; ++i)
                if (lane < 8) zbuf[p][i][cc] = accx[i];   // h(-1) = 0
        }

        // Pair-local barrier: both halves' zbuf writes visible to epilogue.
        asm volatile("bar.sync %0, 64;" :: "r"(p + 1) : "memory");

        // Epilogue (even warp): gates, publish h, then sound release:
        // per-lane fence -> syncwarp (lane->lane0 ordering edge) -> lane0 RED.
        if (half == 0) {
            if (lane < 16) {
                int b_loc = lane >> 2, hc = lane & 3;
                int b2 = (p << 2) + b_loc;
                float zi = zbuf[p][b_loc][0  + hc];
                float zf = zbuf[p][b_loc][4  + hc];
                float zg = zbuf[p][b_loc][8  + hc];
                float zo = zbuf[p][b_loc][12 + hc];
                float cn = sigm(zf) * creg + sigm(zi) * tanh_fast(zg);
                float hn = sigm(zo) * tanh_fast(cn);
                creg = cn;
                int col = (sl << 2) + hc;
                int s_cur = dd ? (SS - 1 - t) : t;
                g_hbuf[dd][t & 1][(b2 << 8) + col] = hn;
                out[((size_t)b2 * SS + s_cur) * (2 * FF) + dd * FF + col] = hn;
                if (t == SS - 1 && write_finals) {
                    size_t base = (size_t)BB * SS * 2 * FF + (size_t)dd * 2 * BB * FF;
                    out[base + b2 * FF + col]           = cn;  // c_final
                    out[base + BB * FF + b2 * FF + col] = hn;  // h_final
                }
                __threadfence();             // own h-stores visible at gpu scope
            }
            __syncwarp();                    // orders ALL epi lanes' fenced
                                             // stores before lane0's arrival
            if (lane == 0)
                atomicAdd(&g_cnt[dd][0], 1u);   // unused return -> REDG
        }
        if (t == SS - 1) break;

        // Stage x(t+1) into private buffer + x-project (hides under the poll).
        {
            int sn = dd ? (SS - 2 - t) : (t + 1);
            __syncwarp();                    // WAR vs this step's h-dot reads
#pragma unroll
            for (int r = 0; r < 8; ++r) {
                int m = (r << 5) + lane;
                int i = m >> 6, off = m & 63;
                int ksrc = ((off & 3) << 6) + ((off >> 2) << 2);
                *(float4*)(hw + (m << 2)) =
                    *(const float4*)(x + ((size_t)((p << 2) + i) * SS + sn) * HH + ksrc);
            }
            __syncwarp();
#pragma unroll
            for (int i = 0; i < 4; ++i) {
                const float* vp = hw + (i << 8) + (kc << 2);
                unsigned long long a0 = 0ull, a1 = 0ull;
#pragma unroll
                for (int j = 0; j < 16; ++j) {
                    ulonglong2 v = *(const ulonglong2*)(vp + (j << 4));
                    fma2(a0, v.x, wi2[2 * j]);
                    fma2(a1, v.y, wi2[2 * j + 1]);
                }
                float s = red2(a0) + red2(a1);
                s += __shfl_xor_sync(0xffffffffu, s, 8);
                s += __shfl_xor_sync(0xffffffffu, s, 16);
                accx[i] = bcc + s;
            }
        }
    }
}

extern "C" void kernel_launch(void* const* d_in, const int* in_sizes, int n_in,
                              void* d_out, int out_size) {
    const float* x     = (const float*)d_in[0];
    const float* Wi_fw = (const float*)d_in[1];
    const float* Wh_fw = (const float*)d_in[2];
    const float* b_fw  = (const float*)d_in[3];
    const float* Wi_rv = (const float*)d_in[4];
    const float* Wh_rv = (const float*)d_in[5];
    const float* b_rv  = (const float*)d_in[6];
    float* out = (float*)d_out;

    int write_finals = (out_size >= (int)((size_t)BB * SS * 2 * FF + 4 * BB * FF)) ? 1 : 0;

    lstm_init_kernel<<<1, 32>>>();
    lstm_scan_kernel<<<2 * NSL, NT>>>(x, Wi_fw, Wh_fw, b_fw,
                                      Wi_rv, Wh_rv, b_rv, out, write_finals);
}